// round 6
// baseline (speedup 1.0000x reference)
#include <cuda_runtime.h>
#include <cstdint>
#include <cstddef>

#define Lq 2048
#define Hh 16
#define Cc 64
#define Bb 2

// Output layout: [context (B,L,H*C)] [scores (B,H,L,L)] [weights (B,H,L,L)]
#define OFF_S  ((size_t)Bb * Lq * Hh * Cc)
#define NSCORE ((size_t)Bb * Hh * Lq * Lq)
#define OFF_W  (OFF_S + NSCORE)

#define PADA 68
#define PADV 133

#define SMEM_SCORES ((64 * PADA + 128 * PADA) * 4)   // Qs + Ks = 52224 B
#define SMEM_AV     ((64 * PADA + 64 * PADV) * 4)    // Ws + Vt = 51456 B

__device__ int g_mask_kind;  // 0 = u8/bool, 1 = int32, 2 = float32

// Per-row exp-sum partials: [bh][i][32 slots] (16 j-blocks x 2 warps). 8 MB.
__device__ float g_rowsum_part[(size_t)Bb * Hh * Lq * 32];

// ---------------------------------------------------------------------------
__global__ void detect_mask_kernel(const void* __restrict__ m) {
    if (threadIdx.x == 0 && blockIdx.x == 0) {
        const unsigned int* w = (const unsigned int*)m;
        bool i32 = true, f32 = true;
        for (int t = 0; t < 256; t++) {
            unsigned int v = w[t];
            if (v > 1u) i32 = false;
            if (v != 0u && v != 0x3F800000u) f32 = false;
        }
        g_mask_kind = i32 ? 1 : (f32 ? 2 : 0);
    }
}

// ---------------------------------------------------------------------------
__device__ __forceinline__ float f2tf(float x) {
    unsigned r;
    asm("cvt.rna.tf32.f32 %0, %1;" : "=r"(r) : "f"(x));
    return __uint_as_float(r);
}

__device__ __forceinline__ void mma_tf32(float (&d)[4], const float (&a)[4],
                                         float b0, float b1) {
    asm volatile(
        "mma.sync.aligned.m16n8k8.row.col.f32.tf32.tf32.f32 "
        "{%0,%1,%2,%3}, {%4,%5,%6,%7}, {%8,%9}, {%0,%1,%2,%3};"
        : "+f"(d[0]), "+f"(d[1]), "+f"(d[2]), "+f"(d[3])
        : "r"(__float_as_uint(a[0])), "r"(__float_as_uint(a[1])),
          "r"(__float_as_uint(a[2])), "r"(__float_as_uint(a[3])),
          "r"(__float_as_uint(b0)), "r"(__float_as_uint(b1)));
}

__device__ __forceinline__ float2 mask2f(int kind, const void* mask, size_t off) {
    float2 r;
    if (kind == 1) {
        const int2 m = *(const int2*)((const int*)mask + off);
        r.x = m.x ? 1.f : 0.f; r.y = m.y ? 1.f : 0.f;
    } else if (kind == 2) {
        const float2 m = *(const float2*)((const float*)mask + off);
        r.x = (m.x != 0.f) ? 1.f : 0.f; r.y = (m.y != 0.f) ? 1.f : 0.f;
    } else {
        const uchar2 m = *(const uchar2*)((const unsigned char*)mask + off);
        r.x = m.x ? 1.f : 0.f; r.y = m.y ? 1.f : 0.f;
    }
    return r;
}

__device__ __forceinline__ float4 mask4f(int kind, const void* mask, size_t off) {
    float4 r;
    if (kind == 1) {
        const int4 m = *(const int4*)((const int*)mask + off);
        r.x = m.x ? 1.f : 0.f; r.y = m.y ? 1.f : 0.f;
        r.z = m.z ? 1.f : 0.f; r.w = m.w ? 1.f : 0.f;
    } else if (kind == 2) {
        const float4 m = *(const float4*)((const float*)mask + off);
        r.x = (m.x != 0.f) ? 1.f : 0.f; r.y = (m.y != 0.f) ? 1.f : 0.f;
        r.z = (m.z != 0.f) ? 1.f : 0.f; r.w = (m.w != 0.f) ? 1.f : 0.f;
    } else {
        const uchar4 m = *(const uchar4*)((const unsigned char*)mask + off);
        r.x = m.x ? 1.f : 0.f; r.y = m.y ? 1.f : 0.f;
        r.z = m.z ? 1.f : 0.f; r.w = m.w ? 1.f : 0.f;
    }
    return r;
}

// ---------------------------------------------------------------------------
// Kernel 1: scores = QK^T + edge; also emit per-row partial sums of
// mask*exp(score/8) into g_rowsum_part (deterministic slots, no atomics).
// CTA tile 64(i) x 128(j), 8 warps as 4(i) x 2(j).
// ---------------------------------------------------------------------------
__global__ __launch_bounds__(256, 3) void scores_kernel(
    const float* __restrict__ q, const float* __restrict__ k,
    const float* __restrict__ edge, const void* __restrict__ mask,
    float* __restrict__ out_scores) {
    extern __shared__ float sm[];
    float* Qs = sm;                 // [64][PADA]  : [i][c]
    float* Ks = sm + 64 * PADA;     // [128][PADA] : [j][c]

    const int bh = blockIdx.z;
    const int b = bh >> 4, h = bh & 15;
    const int i0 = blockIdx.y << 6;
    const int j0 = blockIdx.x << 7;
    const int tid = threadIdx.x;
    const int kind = g_mask_kind;

#pragma unroll
    for (int r = 0; r < 4; r++) {
        const int idx = r * 256 + tid;
        const int row = idx >> 4;
        const int c4 = (idx & 15) * 4;
        const float4 vq = *(const float4*)(q +
            ((size_t)(b * Lq + i0 + row) * Hh + h) * Cc + c4);
        float* d = &Qs[row * PADA + c4];
        d[0] = f2tf(vq.x); d[1] = f2tf(vq.y);
        d[2] = f2tf(vq.z); d[3] = f2tf(vq.w);
    }
#pragma unroll
    for (int r = 0; r < 8; r++) {
        const int idx = r * 256 + tid;
        const int row = idx >> 4;
        const int c4 = (idx & 15) * 4;
        const float4 vk = *(const float4*)(k +
            ((size_t)(b * Lq + j0 + row) * Hh + h) * Cc + c4);
        float* d = &Ks[row * PADA + c4];
        d[0] = f2tf(vk.x); d[1] = f2tf(vk.y);
        d[2] = f2tf(vk.z); d[3] = f2tf(vk.w);
    }
    __syncthreads();

    const int warp = tid >> 5, lane = tid & 31;
    const int wi = warp >> 1, wj = warp & 1;
    const int ibase = wi * 16, jbase = wj * 64;
    const int gid = lane >> 2, qid = lane & 3;

    float acc[8][4] = {};

#pragma unroll
    for (int kk = 0; kk < 8; kk++) {
        const int k0 = kk * 8;
        float a[4];
        const int rr = ibase + gid;
        a[0] = Qs[rr * PADA + k0 + qid];
        a[1] = Qs[(rr + 8) * PADA + k0 + qid];
        a[2] = Qs[rr * PADA + k0 + qid + 4];
        a[3] = Qs[(rr + 8) * PADA + k0 + qid + 4];
#pragma unroll
        for (int n = 0; n < 8; n++) {
            const int cc = jbase + n * 8 + gid;
            const float b0 = Ks[cc * PADA + k0 + qid];
            const float b1 = Ks[cc * PADA + k0 + qid + 4];
            mma_tf32(acc[n], a, b0, b1);
        }
    }

    const int r0 = i0 + ibase + gid;
    const int r1 = r0 + 8;
    float p0 = 0.0f, p1 = 0.0f;

#pragma unroll
    for (int n = 0; n < 8; n++) {
        const int j = j0 + jbase + n * 8 + 2 * qid;
        const size_t e0 = ((size_t)h * Lq + r0) * Lq + j;
        const size_t s0 = ((size_t)bh * Lq + r0) * Lq + j;
        const float2 ea = *(const float2*)(edge + e0);
        const float2 eb = *(const float2*)(edge + e0 + 8 * (size_t)Lq);
        float2 oa, ob;
        oa.x = acc[n][0] + ea.x; oa.y = acc[n][1] + ea.y;
        ob.x = acc[n][2] + eb.x; ob.y = acc[n][3] + eb.y;
        *(float2*)(out_scores + s0) = oa;
        *(float2*)(out_scores + s0 + 8 * (size_t)Lq) = ob;
        const float2 ma = mask2f(kind, mask, ((size_t)(b * Lq + r0)) * Lq + j);
        const float2 mb = mask2f(kind, mask, ((size_t)(b * Lq + r1)) * Lq + j);
        p0 += (ma.x != 0.f ? __expf(oa.x * 0.125f) : 0.f)
            + (ma.y != 0.f ? __expf(oa.y * 0.125f) : 0.f);
        p1 += (mb.x != 0.f ? __expf(ob.x * 0.125f) : 0.f)
            + (mb.y != 0.f ? __expf(ob.y * 0.125f) : 0.f);
    }

    // Reduce across the 4 qid lanes of each row
    p0 += __shfl_xor_sync(0xffffffffu, p0, 1);
    p0 += __shfl_xor_sync(0xffffffffu, p0, 2);
    p1 += __shfl_xor_sync(0xffffffffu, p1, 1);
    p1 += __shfl_xor_sync(0xffffffffu, p1, 2);
    if (qid == 0) {
        const int slot = blockIdx.x * 2 + wj;
        g_rowsum_part[((size_t)bh * Lq + r0) * 32 + slot] = p0;
        g_rowsum_part[((size_t)bh * Lq + r1) * 32 + slot] = p1;
    }
}

// ---------------------------------------------------------------------------
// Kernel 2 (fused normalize + AV): w = mask*exp(s/8)*inv, write weights,
// ctx = W*V via TF32 mma. CTA tile 64(i) x 64(c), j chunks of 64.
// ---------------------------------------------------------------------------
__global__ __launch_bounds__(256, 4) void av_kernel(
    const float* __restrict__ scores, const void* __restrict__ mask,
    const float* __restrict__ v, float* __restrict__ weights,
    float* __restrict__ ctx) {
    extern __shared__ float sm[];
    float* Ws = sm;                // [64][PADA] : [i][j]  (tf32 weights)
    float* Vt = sm + 64 * PADA;    // [64][PADV] : [c][j]
    __shared__ float invs[64];

    const int bh = blockIdx.y;
    const int b = bh >> 4, h = bh & 15;
    const int i0 = blockIdx.x << 6;
    const int tid = threadIdx.x;
    const int warp = tid >> 5, lane = tid & 31;
    const int wi = warp >> 1, wc = warp & 1;
    const int ibase = wi * 16, cbase = wc * 32;
    const int gid = lane >> 2, qid = lane & 3;
    const int kind = g_mask_kind;

    // Fold 32 partials -> inv per row
    if (tid < 64) {
        const float* p = &g_rowsum_part[((size_t)bh * Lq + i0 + tid) * 32];
        float s = 0.0f;
#pragma unroll
        for (int t = 0; t < 8; t++) {
            const float4 v4 = *(const float4*)(p + t * 4);
            s += v4.x + v4.y + v4.z + v4.w;
        }
        invs[tid] = (s != 0.0f) ? 1.0f / s : 0.0f;
    }

    float acc[4][4] = {};

    for (int j0 = 0; j0 < Lq; j0 += 64) {
        __syncthreads();
        // Stage W tile: read scores, compute w, write weights, stash tf32 w.
#pragma unroll
        for (int r = 0; r < 4; r++) {
            const int idx = r * 256 + tid;
            const int row = idx >> 4;
            const int c4 = (idx & 15) * 4;
            const size_t gs = ((size_t)bh * Lq + i0 + row) * Lq + j0 + c4;
            const float4 s4 = *(const float4*)(scores + gs);
            const float4 m4 = mask4f(kind, mask,
                ((size_t)(b * Lq + i0 + row)) * Lq + j0 + c4);
            const float iv = invs[row];
            float4 w4;
            w4.x = (m4.x != 0.f) ? __expf(s4.x * 0.125f) * iv : 0.f;
            w4.y = (m4.y != 0.f) ? __expf(s4.y * 0.125f) * iv : 0.f;
            w4.z = (m4.z != 0.f) ? __expf(s4.z * 0.125f) * iv : 0.f;
            w4.w = (m4.w != 0.f) ? __expf(s4.w * 0.125f) * iv : 0.f;
            *(float4*)(weights + gs) = w4;
            float4 wt;
            wt.x = f2tf(w4.x); wt.y = f2tf(w4.y);
            wt.z = f2tf(w4.z); wt.w = f2tf(w4.w);
            *(float4*)&Ws[row * PADA + c4] = wt;
        }
        // Stage V tile transposed: Vt[c][j]
#pragma unroll
        for (int r = 0; r < 4; r++) {
            const int idx = r * 256 + tid;
            const int jr = idx >> 4;
            const int c4 = (idx & 15) * 4;
            const float4 vv = *(const float4*)(v +
                ((size_t)(b * Lq + j0 + jr) * Hh + h) * Cc + c4);
            Vt[(c4 + 0) * PADV + jr] = f2tf(vv.x);
            Vt[(c4 + 1) * PADV + jr] = f2tf(vv.y);
            Vt[(c4 + 2) * PADV + jr] = f2tf(vv.z);
            Vt[(c4 + 3) * PADV + jr] = f2tf(vv.w);
        }
        __syncthreads();

#pragma unroll
        for (int kk = 0; kk < 8; kk++) {
            const int k0 = kk * 8;
            float a[4];
            const int rr = ibase + gid;
            a[0] = Ws[rr * PADA + k0 + qid];
            a[1] = Ws[(rr + 8) * PADA + k0 + qid];
            a[2] = Ws[rr * PADA + k0 + qid + 4];
            a[3] = Ws[(rr + 8) * PADA + k0 + qid + 4];
#pragma unroll
            for (int n = 0; n < 4; n++) {
                const int cc = cbase + n * 8 + gid;
                const float b0 = Vt[cc * PADV + k0 + qid];
                const float b1 = Vt[cc * PADV + k0 + qid + 4];
                mma_tf32(acc[n], a, b0, b1);
            }
        }
    }

#pragma unroll
    for (int n = 0; n < 4; n++) {
        const int i = i0 + ibase + gid;
        const int c = h * Cc + cbase + n * 8 + 2 * qid;
        float2 oa, ob;
        oa.x = acc[n][0]; oa.y = acc[n][1];
        ob.x = acc[n][2]; ob.y = acc[n][3];
        *(float2*)(ctx + ((size_t)(b * Lq + i)) * (Hh * Cc) + c) = oa;
        *(float2*)(ctx + ((size_t)(b * Lq + i + 8)) * (Hh * Cc) + c) = ob;
    }
}

// ---------------------------------------------------------------------------
extern "C" void kernel_launch(void* const* d_in, const int* in_sizes, int n_in,
                              void* d_out, int out_size) {
    (void)in_sizes; (void)n_in; (void)out_size;
    const float* q    = (const float*)d_in[0];
    const float* k    = (const float*)d_in[1];
    const float* v    = (const float*)d_in[2];
    const void*  mask = d_in[3];
    const float* edge = (const float*)d_in[4];

    float* out     = (float*)d_out;
    float* ctx     = out;
    float* scores  = out + OFF_S;
    float* weights = out + OFF_W;

    cudaFuncSetAttribute(scores_kernel,
        cudaFuncAttributeMaxDynamicSharedMemorySize, SMEM_SCORES);
    cudaFuncSetAttribute(av_kernel,
        cudaFuncAttributeMaxDynamicSharedMemorySize, SMEM_AV);

    detect_mask_kernel<<<1, 32>>>(mask);

    {
        dim3 grid(Lq / 128, Lq / 64, Bb * Hh);
        scores_kernel<<<grid, 256, SMEM_SCORES>>>(q, k, edge, mask, scores);
    }
    {
        dim3 grid(Lq / 64, Bb * Hh);
        av_kernel<<<grid, 256, SMEM_AV>>>(scores, mask, v, weights, ctx);
    }
}

// round 7
// speedup vs baseline: 1.3070x; 1.3070x over previous
#include <cuda_runtime.h>
#include <cstdint>
#include <cstddef>

#define Lq 2048
#define Hh 16
#define Cc 64
#define Bb 2

// Output layout: [context (B,L,H*C)] [scores (B,H,L,L)] [weights (B,H,L,L)]
#define OFF_S  ((size_t)Bb * Lq * Hh * Cc)
#define NSCORE ((size_t)Bb * Hh * Lq * Lq)
#define OFF_W  (OFF_S + NSCORE)

#define PADA 68
#define AVPAD 72      // 72 % 32 == 8 -> conflict-free frag reads; 288B rows (16B mult.)
#define AV_STAGE (2 * 64 * AVPAD)                 // floats per stage (W + V)
#define SMEM_SCORES (2 * 128 * PADA * 4)          // Qs + Ks = 69632 B
#define SMEM_AV     (2 * AV_STAGE * 4)            // 73728 B

__device__ int g_mask_kind;  // 0 = u8/bool, 1 = int32, 2 = float32

// ---------------------------------------------------------------------------
__global__ void detect_mask_kernel(const void* __restrict__ m) {
    const unsigned int* w = (const unsigned int*)m;
    const int lane = threadIdx.x;
    bool i32 = true, f32 = true;
    for (int t = lane; t < 256; t += 32) {
        const unsigned int v = w[t];
        i32 = i32 && (v <= 1u);
        f32 = f32 && (v == 0u || v == 0x3F800000u);
    }
    const unsigned bi = __ballot_sync(0xffffffffu, i32);
    const unsigned bf = __ballot_sync(0xffffffffu, f32);
    if (lane == 0)
        g_mask_kind = (bi == 0xffffffffu) ? 1 : ((bf == 0xffffffffu) ? 2 : 0);
}

// ---------------------------------------------------------------------------
__device__ __forceinline__ float f2tf(float x) {
    unsigned r;
    asm("cvt.rna.tf32.f32 %0, %1;" : "=r"(r) : "f"(x));
    return __uint_as_float(r);
}

__device__ __forceinline__ void mma_tf32(float (&d)[4], const float (&a)[4],
                                         float b0, float b1) {
    asm volatile(
        "mma.sync.aligned.m16n8k8.row.col.f32.tf32.tf32.f32 "
        "{%0,%1,%2,%3}, {%4,%5,%6,%7}, {%8,%9}, {%0,%1,%2,%3};"
        : "+f"(d[0]), "+f"(d[1]), "+f"(d[2]), "+f"(d[3])
        : "r"(__float_as_uint(a[0])), "r"(__float_as_uint(a[1])),
          "r"(__float_as_uint(a[2])), "r"(__float_as_uint(a[3])),
          "r"(__float_as_uint(b0)), "r"(__float_as_uint(b1)));
}

__device__ __forceinline__ void cp16(void* s, const void* g) {
    const unsigned saddr = (unsigned)__cvta_generic_to_shared(s);
    asm volatile("cp.async.cg.shared.global [%0], [%1], 16;"
                 :: "r"(saddr), "l"(g));
}

// ---------------------------------------------------------------------------
// Kernel 1 (R3 layout): scores = QK^T + edge. 128x128 tile, K=64 one pass.
// 8 warps as 4(i) x 2(j); warp = 32i x 64j. rna tf32 conversion kept.
// ---------------------------------------------------------------------------
__global__ __launch_bounds__(256) void scores_kernel(
    const float* __restrict__ q, const float* __restrict__ k,
    const float* __restrict__ edge, float* __restrict__ out_scores) {
    extern __shared__ float sm[];
    float* Qs = sm;                 // [128][PADA] : [i][c]
    float* Ks = sm + 128 * PADA;    // [128][PADA] : [j][c]

    const int bh = blockIdx.z;
    const int b = bh >> 4, h = bh & 15;
    const int i0 = blockIdx.y << 7;
    const int j0 = blockIdx.x << 7;
    const int tid = threadIdx.x;

#pragma unroll
    for (int r = 0; r < 8; r++) {
        const int idx = r * 256 + tid;
        const int row = idx >> 4;
        const int c4 = (idx & 15) * 4;
        const float4 vq = *(const float4*)(q +
            ((size_t)(b * Lq + i0 + row) * Hh + h) * Cc + c4);
        float* dq = &Qs[row * PADA + c4];
        dq[0] = f2tf(vq.x); dq[1] = f2tf(vq.y);
        dq[2] = f2tf(vq.z); dq[3] = f2tf(vq.w);
        const float4 vk = *(const float4*)(k +
            ((size_t)(b * Lq + j0 + row) * Hh + h) * Cc + c4);
        float* dk = &Ks[row * PADA + c4];
        dk[0] = f2tf(vk.x); dk[1] = f2tf(vk.y);
        dk[2] = f2tf(vk.z); dk[3] = f2tf(vk.w);
    }
    __syncthreads();

    const int warp = tid >> 5, lane = tid & 31;
    const int wi = warp >> 1, wj = warp & 1;
    const int ibase = wi * 32, jbase = wj * 64;
    const int gid = lane >> 2, qid = lane & 3;

    float acc[2][8][4] = {};

#pragma unroll
    for (int kk = 0; kk < 8; kk++) {
        const int k0 = kk * 8;
        float a[2][4];
#pragma unroll
        for (int m = 0; m < 2; m++) {
            const int rr = ibase + m * 16 + gid;
            a[m][0] = Qs[rr * PADA + k0 + qid];
            a[m][1] = Qs[(rr + 8) * PADA + k0 + qid];
            a[m][2] = Qs[rr * PADA + k0 + qid + 4];
            a[m][3] = Qs[(rr + 8) * PADA + k0 + qid + 4];
        }
#pragma unroll
        for (int n = 0; n < 8; n++) {
            const int cc = jbase + n * 8 + gid;
            const float b0 = Ks[cc * PADA + k0 + qid];
            const float b1 = Ks[cc * PADA + k0 + qid + 4];
            mma_tf32(acc[0][n], a[0], b0, b1);
            mma_tf32(acc[1][n], a[1], b0, b1);
        }
    }

#pragma unroll
    for (int m = 0; m < 2; m++) {
#pragma unroll
        for (int n = 0; n < 8; n++) {
            const int i = i0 + ibase + m * 16 + gid;
            const int j = j0 + jbase + n * 8 + 2 * qid;
            const size_t e0 = ((size_t)h * Lq + i) * Lq + j;
            const size_t s0 = ((size_t)bh * Lq + i) * Lq + j;
            const float2 ea = *(const float2*)(edge + e0);
            const float2 eb = *(const float2*)(edge + e0 + 8 * (size_t)Lq);
            float2 oa, ob;
            oa.x = acc[m][n][0] + ea.x; oa.y = acc[m][n][1] + ea.y;
            ob.x = acc[m][n][2] + eb.x; ob.y = acc[m][n][3] + eb.y;
            *(float2*)(out_scores + s0) = oa;
            *(float2*)(out_scores + s0 + 8 * (size_t)Lq) = ob;
        }
    }
}

// ---------------------------------------------------------------------------
// Kernel 2: masked softmax. One 256-thread block per (b,h,i) row.
// ---------------------------------------------------------------------------
__global__ __launch_bounds__(256) void softmax_kernel(
    const float* __restrict__ scores, const void* __restrict__ mask,
    float* __restrict__ wout) {
    const int row = blockIdx.x;
    const int bh = row >> 11;
    const int i  = row & (Lq - 1);
    const int b  = bh >> 4;
    const size_t soff = (size_t)row * Lq;
    const size_t moff = ((size_t)(b * Lq + i)) * Lq;
    const int tid = threadIdx.x;
    const int kind = g_mask_kind;

    const float4* sp = (const float4*)(scores + soff);
    const float4 s0 = sp[tid];
    const float4 s1 = sp[256 + tid];

    float mb[8];
    if (kind == 1) {
        const int4* mp = (const int4*)((const int*)mask + moff);
        const int4 m0 = mp[tid], m1 = mp[256 + tid];
        mb[0] = m0.x ? 1.f : 0.f; mb[1] = m0.y ? 1.f : 0.f;
        mb[2] = m0.z ? 1.f : 0.f; mb[3] = m0.w ? 1.f : 0.f;
        mb[4] = m1.x ? 1.f : 0.f; mb[5] = m1.y ? 1.f : 0.f;
        mb[6] = m1.z ? 1.f : 0.f; mb[7] = m1.w ? 1.f : 0.f;
    } else if (kind == 2) {
        const float4* mp = (const float4*)((const float*)mask + moff);
        const float4 m0 = mp[tid], m1 = mp[256 + tid];
        mb[0] = (m0.x != 0.f); mb[1] = (m0.y != 0.f);
        mb[2] = (m0.z != 0.f); mb[3] = (m0.w != 0.f);
        mb[4] = (m1.x != 0.f); mb[5] = (m1.y != 0.f);
        mb[6] = (m1.z != 0.f); mb[7] = (m1.w != 0.f);
    } else {
        const uchar4* mp = (const uchar4*)((const unsigned char*)mask + moff);
        const uchar4 m0 = mp[tid], m1 = mp[256 + tid];
        mb[0] = m0.x ? 1.f : 0.f; mb[1] = m0.y ? 1.f : 0.f;
        mb[2] = m0.z ? 1.f : 0.f; mb[3] = m0.w ? 1.f : 0.f;
        mb[4] = m1.x ? 1.f : 0.f; mb[5] = m1.y ? 1.f : 0.f;
        mb[6] = m1.z ? 1.f : 0.f; mb[7] = m1.w ? 1.f : 0.f;
    }

    const float sv[8] = {s0.x, s0.y, s0.z, s0.w, s1.x, s1.y, s1.z, s1.w};
    float x[8];
#pragma unroll
    for (int t = 0; t < 8; t++)
        x[t] = (mb[t] != 0.f) ? sv[t] * 0.125f : -1e18f;

    float mx = x[0];
#pragma unroll
    for (int t = 1; t < 8; t++) mx = fmaxf(mx, x[t]);
#pragma unroll
    for (int o = 16; o; o >>= 1) mx = fmaxf(mx, __shfl_xor_sync(0xffffffffu, mx, o));

    __shared__ float red_max[8];
    __shared__ float red_sum[8];
    if ((tid & 31) == 0) red_max[tid >> 5] = mx;
    __syncthreads();
    mx = red_max[0];
#pragma unroll
    for (int wi = 1; wi < 8; wi++) mx = fmaxf(mx, red_max[wi]);

    float e[8];
    float s = 0.0f;
#pragma unroll
    for (int t = 0; t < 8; t++) {
        e[t] = __expf(x[t] - mx);
        s += e[t];
    }
#pragma unroll
    for (int o = 16; o; o >>= 1) s += __shfl_xor_sync(0xffffffffu, s, o);
    if ((tid & 31) == 0) red_sum[tid >> 5] = s;
    __syncthreads();
    s = red_sum[0];
#pragma unroll
    for (int wi = 1; wi < 8; wi++) s += red_sum[wi];

    const float inv = 1.0f / s;
    float4 w0, w1;
    w0.x = e[0] * inv * mb[0]; w0.y = e[1] * inv * mb[1];
    w0.z = e[2] * inv * mb[2]; w0.w = e[3] * inv * mb[3];
    w1.x = e[4] * inv * mb[4]; w1.y = e[5] * inv * mb[5];
    w1.z = e[6] * inv * mb[6]; w1.w = e[7] * inv * mb[7];
    float4* wp = (float4*)(wout + soff);
    wp[tid] = w0;
    wp[256 + tid] = w1;
}

// ---------------------------------------------------------------------------
// Kernel 3: ctx = W * V. CTA 64(i) x 64(c), j chunks of 64.
// cp.async double-buffered staging (raw fp32, implicit tf32 in mma),
// conflict-free pad-72 layouts, no transpose.
// ---------------------------------------------------------------------------
__global__ __launch_bounds__(256, 3) void av_kernel(
    const float* __restrict__ w, const float* __restrict__ v,
    float* __restrict__ ctx) {
    extern __shared__ float sm[];

    const int bh = blockIdx.y;
    const int b = bh >> 4, h = bh & 15;
    const int i0 = blockIdx.x << 6;
    const int tid = threadIdx.x;
    const int warp = tid >> 5, lane = tid & 31;
    const int wi = warp >> 1, wc = warp & 1;
    const int ibase = wi * 16, cbase = wc * 32;
    const int gid = lane >> 2, qid = lane & 3;

    const int srow = tid >> 4;   // 0..15
    const int ch4  = (tid & 15) * 4;

    // Stage tile jt into buffer s: W rows then V rows (8 x 16B per thread).
    auto issue = [&](int jt, int s) {
        float* Wb = sm + s * AV_STAGE;
        float* Vb = Wb + 64 * AVPAD;
        const int j0 = jt << 6;
#pragma unroll
        for (int t = 0; t < 4; t++) {
            const int row = t * 16 + srow;
            cp16(&Wb[row * AVPAD + ch4],
                 w + ((size_t)bh * Lq + i0 + row) * Lq + j0 + ch4);
        }
#pragma unroll
        for (int t = 0; t < 4; t++) {
            const int row = t * 16 + srow;
            cp16(&Vb[row * AVPAD + ch4],
                 v + ((size_t)(b * Lq + j0 + row) * Hh + h) * Cc + ch4);
        }
        asm volatile("cp.async.commit_group;");
    };

    float acc[4][4] = {};

    issue(0, 0);

    for (int jt = 0; jt < 32; jt++) {
        const int s = jt & 1;
        if (jt + 1 < 32) {
            issue(jt + 1, s ^ 1);
            asm volatile("cp.async.wait_group 1;");
        } else {
            asm volatile("cp.async.wait_group 0;");
        }
        __syncthreads();

        const float* Wb = sm + s * AV_STAGE;
        const float* Vb = Wb + 64 * AVPAD;

#pragma unroll
        for (int kk = 0; kk < 8; kk++) {
            const int k0 = kk * 8;
            float a[4];
            const int rr = ibase + gid;
            a[0] = Wb[rr * AVPAD + k0 + qid];
            a[1] = Wb[(rr + 8) * AVPAD + k0 + qid];
            a[2] = Wb[rr * AVPAD + k0 + qid + 4];
            a[3] = Wb[(rr + 8) * AVPAD + k0 + qid + 4];
#pragma unroll
            for (int n = 0; n < 4; n++) {
                const int cc = cbase + n * 8 + gid;
                const float b0 = Vb[(k0 + qid) * AVPAD + cc];
                const float b1 = Vb[(k0 + qid + 4) * AVPAD + cc];
                mma_tf32(acc[n], a, b0, b1);
            }
        }
        __syncthreads();
    }

#pragma unroll
    for (int n = 0; n < 4; n++) {
        const int i = i0 + ibase + gid;
        const int c = h * Cc + cbase + n * 8 + 2 * qid;
        float2 oa, ob;
        oa.x = acc[n][0]; oa.y = acc[n][1];
        ob.x = acc[n][2]; ob.y = acc[n][3];
        *(float2*)(ctx + ((size_t)(b * Lq + i)) * (Hh * Cc) + c) = oa;
        *(float2*)(ctx + ((size_t)(b * Lq + i + 8)) * (Hh * Cc) + c) = ob;
    }
}

// ---------------------------------------------------------------------------
extern "C" void kernel_launch(void* const* d_in, const int* in_sizes, int n_in,
                              void* d_out, int out_size) {
    (void)in_sizes; (void)n_in; (void)out_size;
    const float* q    = (const float*)d_in[0];
    const float* k    = (const float*)d_in[1];
    const float* v    = (const float*)d_in[2];
    const void*  mask = d_in[3];
    const float* edge = (const float*)d_in[4];

    float* out     = (float*)d_out;
    float* ctx     = out;
    float* scores  = out + OFF_S;
    float* weights = out + OFF_W;

    cudaFuncSetAttribute(scores_kernel,
        cudaFuncAttributeMaxDynamicSharedMemorySize, SMEM_SCORES);
    cudaFuncSetAttribute(av_kernel,
        cudaFuncAttributeMaxDynamicSharedMemorySize, SMEM_AV);

    detect_mask_kernel<<<1, 32>>>(mask);

    {
        dim3 grid(Lq / 128, Lq / 128, Bb * Hh);
        scores_kernel<<<grid, 256, SMEM_SCORES>>>(q, k, edge, scores);
    }
    {
        softmax_kernel<<<Bb * Hh * Lq, 256>>>(scores, mask, weights);
    }
    {
        dim3 grid(Lq / 64, Bb * Hh);
        av_kernel<<<grid, 256, SMEM_AV>>>(weights, v, ctx);
    }
}

// round 8
// speedup vs baseline: 1.3334x; 1.0202x over previous
#include <cuda_runtime.h>
#include <cstdint>
#include <cstddef>

#define Lq 2048
#define Hh 16
#define Cc 64
#define Bb 2

// Output layout: [context (B,L,H*C)] [scores (B,H,L,L)] [weights (B,H,L,L)]
#define OFF_S  ((size_t)Bb * Lq * Hh * Cc)
#define NSCORE ((size_t)Bb * Hh * Lq * Lq)
#define OFF_W  (OFF_S + NSCORE)

#define PADA 68
#define SMEM_SCORES (2 * 128 * PADA * 4)          // Qs + Ks = 69632 B

// av: 4-stage cp.async pipeline, 32-wide j chunks
#define AVJ 32
#define WROW 36      // 32 + 4 pad: (gid*36 + qid) % 32 hits 32 banks; 144B rows
#define VROW 72      // 64 + 8 pad: (qid*72 + gid-ish) % 32 hits 32 banks; 288B rows
#define AV_STAGE (64 * WROW + AVJ * VROW)         // 4608 floats
#define AV_STAGES 4
#define SMEM_AV (AV_STAGES * AV_STAGE * 4)        // 73728 B

__device__ int g_mask_kind;  // 0 = u8/bool, 1 = int32, 2 = float32

// ---------------------------------------------------------------------------
__global__ void detect_mask_kernel(const void* __restrict__ m) {
    const unsigned int* w = (const unsigned int*)m;
    const int lane = threadIdx.x;
    bool i32 = true, f32 = true;
    for (int t = lane; t < 256; t += 32) {
        const unsigned int v = w[t];
        i32 = i32 && (v <= 1u);
        f32 = f32 && (v == 0u || v == 0x3F800000u);
    }
    const unsigned bi = __ballot_sync(0xffffffffu, i32);
    const unsigned bf = __ballot_sync(0xffffffffu, f32);
    if (lane == 0)
        g_mask_kind = (bi == 0xffffffffu) ? 1 : ((bf == 0xffffffffu) ? 2 : 0);
}

// ---------------------------------------------------------------------------
__device__ __forceinline__ float f2tf(float x) {
    unsigned r;
    asm("cvt.rna.tf32.f32 %0, %1;" : "=r"(r) : "f"(x));
    return __uint_as_float(r);
}

__device__ __forceinline__ void mma_tf32(float (&d)[4], const float (&a)[4],
                                         float b0, float b1) {
    asm volatile(
        "mma.sync.aligned.m16n8k8.row.col.f32.tf32.tf32.f32 "
        "{%0,%1,%2,%3}, {%4,%5,%6,%7}, {%8,%9}, {%0,%1,%2,%3};"
        : "+f"(d[0]), "+f"(d[1]), "+f"(d[2]), "+f"(d[3])
        : "r"(__float_as_uint(a[0])), "r"(__float_as_uint(a[1])),
          "r"(__float_as_uint(a[2])), "r"(__float_as_uint(a[3])),
          "r"(__float_as_uint(b0)), "r"(__float_as_uint(b1)));
}

__device__ __forceinline__ void cp16(void* s, const void* g) {
    const unsigned saddr = (unsigned)__cvta_generic_to_shared(s);
    asm volatile("cp.async.cg.shared.global [%0], [%1], 16;"
                 :: "r"(saddr), "l"(g));
}

// ---------------------------------------------------------------------------
// Kernel 1: scores = QK^T + edge. 128x128 tile, K=64 one pass.
// 8 warps as 4(i) x 2(j); warp = 32i x 64j. rna tf32 staging.
// ---------------------------------------------------------------------------
__global__ __launch_bounds__(256) void scores_kernel(
    const float* __restrict__ q, const float* __restrict__ k,
    const float* __restrict__ edge, float* __restrict__ out_scores) {
    extern __shared__ float sm[];
    float* Qs = sm;                 // [128][PADA] : [i][c]
    float* Ks = sm + 128 * PADA;    // [128][PADA] : [j][c]

    const int bh = blockIdx.z;
    const int b = bh >> 4, h = bh & 15;
    const int i0 = blockIdx.y << 7;
    const int j0 = blockIdx.x << 7;
    const int tid = threadIdx.x;

#pragma unroll
    for (int r = 0; r < 8; r++) {
        const int idx = r * 256 + tid;
        const int row = idx >> 4;
        const int c4 = (idx & 15) * 4;
        const float4 vq = *(const float4*)(q +
            ((size_t)(b * Lq + i0 + row) * Hh + h) * Cc + c4);
        float* dq = &Qs[row * PADA + c4];
        dq[0] = f2tf(vq.x); dq[1] = f2tf(vq.y);
        dq[2] = f2tf(vq.z); dq[3] = f2tf(vq.w);
        const float4 vk = *(const float4*)(k +
            ((size_t)(b * Lq + j0 + row) * Hh + h) * Cc + c4);
        float* dk = &Ks[row * PADA + c4];
        dk[0] = f2tf(vk.x); dk[1] = f2tf(vk.y);
        dk[2] = f2tf(vk.z); dk[3] = f2tf(vk.w);
    }
    __syncthreads();

    const int warp = tid >> 5, lane = tid & 31;
    const int wi = warp >> 1, wj = warp & 1;
    const int ibase = wi * 32, jbase = wj * 64;
    const int gid = lane >> 2, qid = lane & 3;

    float acc[2][8][4] = {};

#pragma unroll
    for (int kk = 0; kk < 8; kk++) {
        const int k0 = kk * 8;
        float a[2][4];
#pragma unroll
        for (int m = 0; m < 2; m++) {
            const int rr = ibase + m * 16 + gid;
            a[m][0] = Qs[rr * PADA + k0 + qid];
            a[m][1] = Qs[(rr + 8) * PADA + k0 + qid];
            a[m][2] = Qs[rr * PADA + k0 + qid + 4];
            a[m][3] = Qs[(rr + 8) * PADA + k0 + qid + 4];
        }
#pragma unroll
        for (int n = 0; n < 8; n++) {
            const int cc = jbase + n * 8 + gid;
            const float b0 = Ks[cc * PADA + k0 + qid];
            const float b1 = Ks[cc * PADA + k0 + qid + 4];
            mma_tf32(acc[0][n], a[0], b0, b1);
            mma_tf32(acc[1][n], a[1], b0, b1);
        }
    }

#pragma unroll
    for (int m = 0; m < 2; m++) {
#pragma unroll
        for (int n = 0; n < 8; n++) {
            const int i = i0 + ibase + m * 16 + gid;
            const int j = j0 + jbase + n * 8 + 2 * qid;
            const size_t e0 = ((size_t)h * Lq + i) * Lq + j;
            const size_t s0 = ((size_t)bh * Lq + i) * Lq + j;
            const float2 ea = *(const float2*)(edge + e0);
            const float2 eb = *(const float2*)(edge + e0 + 8 * (size_t)Lq);
            float2 oa, ob;
            oa.x = acc[m][n][0] + ea.x; oa.y = acc[m][n][1] + ea.y;
            ob.x = acc[m][n][2] + eb.x; ob.y = acc[m][n][3] + eb.y;
            __stcs((float2*)(out_scores + s0), oa);
            __stcs((float2*)(out_scores + s0 + 8 * (size_t)Lq), ob);
        }
    }
}

// ---------------------------------------------------------------------------
// Kernel 2: masked softmax. One 256-thread block per (b,h,i) row.
// ---------------------------------------------------------------------------
__global__ __launch_bounds__(256) void softmax_kernel(
    const float* __restrict__ scores, const void* __restrict__ mask,
    float* __restrict__ wout) {
    const int row = blockIdx.x;
    const int bh = row >> 11;
    const int i  = row & (Lq - 1);
    const int b  = bh >> 4;
    const size_t soff = (size_t)row * Lq;
    const size_t moff = ((size_t)(b * Lq + i)) * Lq;
    const int tid = threadIdx.x;
    const int kind = g_mask_kind;

    const float4* sp = (const float4*)(scores + soff);
    const float4 s0 = __ldcs(sp + tid);
    const float4 s1 = __ldcs(sp + 256 + tid);

    float mb[8];
    if (kind == 1) {
        const int4* mp = (const int4*)((const int*)mask + moff);
        const int4 m0 = mp[tid], m1 = mp[256 + tid];
        mb[0] = m0.x ? 1.f : 0.f; mb[1] = m0.y ? 1.f : 0.f;
        mb[2] = m0.z ? 1.f : 0.f; mb[3] = m0.w ? 1.f : 0.f;
        mb[4] = m1.x ? 1.f : 0.f; mb[5] = m1.y ? 1.f : 0.f;
        mb[6] = m1.z ? 1.f : 0.f; mb[7] = m1.w ? 1.f : 0.f;
    } else if (kind == 2) {
        const float4* mp = (const float4*)((const float*)mask + moff);
        const float4 m0 = mp[tid], m1 = mp[256 + tid];
        mb[0] = (m0.x != 0.f); mb[1] = (m0.y != 0.f);
        mb[2] = (m0.z != 0.f); mb[3] = (m0.w != 0.f);
        mb[4] = (m1.x != 0.f); mb[5] = (m1.y != 0.f);
        mb[6] = (m1.z != 0.f); mb[7] = (m1.w != 0.f);
    } else {
        const uchar4* mp = (const uchar4*)((const unsigned char*)mask + moff);
        const uchar4 m0 = mp[tid], m1 = mp[256 + tid];
        mb[0] = m0.x ? 1.f : 0.f; mb[1] = m0.y ? 1.f : 0.f;
        mb[2] = m0.z ? 1.f : 0.f; mb[3] = m0.w ? 1.f : 0.f;
        mb[4] = m1.x ? 1.f : 0.f; mb[5] = m1.y ? 1.f : 0.f;
        mb[6] = m1.z ? 1.f : 0.f; mb[7] = m1.w ? 1.f : 0.f;
    }

    const float sv[8] = {s0.x, s0.y, s0.z, s0.w, s1.x, s1.y, s1.z, s1.w};
    float x[8];
#pragma unroll
    for (int t = 0; t < 8; t++)
        x[t] = (mb[t] != 0.f) ? sv[t] * 0.125f : -1e18f;

    float mx = x[0];
#pragma unroll
    for (int t = 1; t < 8; t++) mx = fmaxf(mx, x[t]);
#pragma unroll
    for (int o = 16; o; o >>= 1) mx = fmaxf(mx, __shfl_xor_sync(0xffffffffu, mx, o));

    __shared__ float red_max[8];
    __shared__ float red_sum[8];
    if ((tid & 31) == 0) red_max[tid >> 5] = mx;
    __syncthreads();
    mx = red_max[0];
#pragma unroll
    for (int wi = 1; wi < 8; wi++) mx = fmaxf(mx, red_max[wi]);

    float e[8];
    float s = 0.0f;
#pragma unroll
    for (int t = 0; t < 8; t++) {
        e[t] = __expf(x[t] - mx);
        s += e[t];
    }
#pragma unroll
    for (int o = 16; o; o >>= 1) s += __shfl_xor_sync(0xffffffffu, s, o);
    if ((tid & 31) == 0) red_sum[tid >> 5] = s;
    __syncthreads();
    s = red_sum[0];
#pragma unroll
    for (int wi = 1; wi < 8; wi++) s += red_sum[wi];

    const float inv = 1.0f / s;
    float4 w0, w1;
    w0.x = e[0] * inv * mb[0]; w0.y = e[1] * inv * mb[1];
    w0.z = e[2] * inv * mb[2]; w0.w = e[3] * inv * mb[3];
    w1.x = e[4] * inv * mb[4]; w1.y = e[5] * inv * mb[5];
    w1.z = e[6] * inv * mb[6]; w1.w = e[7] * inv * mb[7];
    float4* wp = (float4*)(wout + soff);
    __stcs(wp + tid, w0);
    __stcs(wp + 256 + tid, w1);
}

// ---------------------------------------------------------------------------
// Kernel 3: ctx = W * V. CTA 64(i) x 64(c), j chunks of 32.
// 4-stage cp.async pipeline, ONE syncthreads per iteration.
// rna tf32 rounding applied on register fragments.
// ---------------------------------------------------------------------------
__global__ __launch_bounds__(256, 3) void av_kernel(
    const float* __restrict__ w, const float* __restrict__ v,
    float* __restrict__ ctx) {
    extern __shared__ float sm[];

    const int bh = blockIdx.y;
    const int b = bh >> 4, h = bh & 15;
    const int i0 = blockIdx.x << 6;
    const int tid = threadIdx.x;
    const int warp = tid >> 5, lane = tid & 31;
    const int wi = warp >> 1, wc = warp & 1;
    const int ibase = wi * 16, cbase = wc * 32;
    const int gid = lane >> 2, qid = lane & 3;

    // Staging maps
    const int wrow = tid >> 3;            // 0..31 -> two rows per thread pass
    const int wc4  = (tid & 7) * 4;       // 0..28
    const int vrow = tid >> 4;            // 0..15
    const int vc4  = (tid & 15) * 4;      // 0..60

    auto issue = [&](int jt, int s) {
        float* Wb = sm + s * AV_STAGE;
        float* Vb = Wb + 64 * WROW;
        const int j0 = jt * AVJ;
#pragma unroll
        for (int t = 0; t < 2; t++) {
            const int row = t * 32 + wrow;
            cp16(&Wb[row * WROW + wc4],
                 w + ((size_t)bh * Lq + i0 + row) * Lq + j0 + wc4);
        }
#pragma unroll
        for (int t = 0; t < 2; t++) {
            const int row = t * 16 + vrow;
            cp16(&Vb[row * VROW + vc4],
                 v + ((size_t)(b * Lq + j0 + row) * Hh + h) * Cc + vc4);
        }
        asm volatile("cp.async.commit_group;");
    };

    float acc[4][4] = {};

    const int NT = Lq / AVJ;   // 64
    issue(0, 0);
    issue(1, 1);
    issue(2, 2);

    for (int jt = 0; jt < NT; jt++) {
        asm volatile("cp.async.wait_group 2;");
        __syncthreads();
        if (jt + 3 < NT) {
            issue(jt + 3, (jt + 3) & 3);
        } else {
            asm volatile("cp.async.commit_group;");   // empty group keeps counts valid
        }

        const float* Wb = sm + (jt & 3) * AV_STAGE;
        const float* Vb = Wb + 64 * WROW;

#pragma unroll
        for (int kk = 0; kk < 4; kk++) {
            const int k0 = kk * 8;
            float a[4];
            const int rr = ibase + gid;
            a[0] = f2tf(Wb[rr * WROW + k0 + qid]);
            a[1] = f2tf(Wb[(rr + 8) * WROW + k0 + qid]);
            a[2] = f2tf(Wb[rr * WROW + k0 + qid + 4]);
            a[3] = f2tf(Wb[(rr + 8) * WROW + k0 + qid + 4]);
#pragma unroll
            for (int n = 0; n < 4; n++) {
                const int cc = cbase + n * 8 + gid;
                const float b0 = f2tf(Vb[(k0 + qid) * VROW + cc]);
                const float b1 = f2tf(Vb[(k0 + qid + 4) * VROW + cc]);
                mma_tf32(acc[n], a, b0, b1);
            }
        }
    }

#pragma unroll
    for (int n = 0; n < 4; n++) {
        const int i = i0 + ibase + gid;
        const int c = h * Cc + cbase + n * 8 + 2 * qid;
        float2 oa, ob;
        oa.x = acc[n][0]; oa.y = acc[n][1];
        ob.x = acc[n][2]; ob.y = acc[n][3];
        *(float2*)(ctx + ((size_t)(b * Lq + i)) * (Hh * Cc) + c) = oa;
        *(float2*)(ctx + ((size_t)(b * Lq + i + 8)) * (Hh * Cc) + c) = ob;
    }
}

// ---------------------------------------------------------------------------
extern "C" void kernel_launch(void* const* d_in, const int* in_sizes, int n_in,
                              void* d_out, int out_size) {
    (void)in_sizes; (void)n_in; (void)out_size;
    const float* q    = (const float*)d_in[0];
    const float* k    = (const float*)d_in[1];
    const float* v    = (const float*)d_in[2];
    const void*  mask = d_in[3];
    const float* edge = (const float*)d_in[4];

    float* out     = (float*)d_out;
    float* ctx     = out;
    float* scores  = out + OFF_S;
    float* weights = out + OFF_W;

    cudaFuncSetAttribute(scores_kernel,
        cudaFuncAttributeMaxDynamicSharedMemorySize, SMEM_SCORES);
    cudaFuncSetAttribute(av_kernel,
        cudaFuncAttributeMaxDynamicSharedMemorySize, SMEM_AV);

    detect_mask_kernel<<<1, 32>>>(mask);

    {
        dim3 grid(Lq / 128, Lq / 128, Bb * Hh);
        scores_kernel<<<grid, 256, SMEM_SCORES>>>(q, k, edge, scores);
    }
    {
        softmax_kernel<<<Bb * Hh * Lq, 256>>>(scores, mask, weights);
    }
    {
        dim3 grid(Lq / 64, Bb * Hh);
        av_kernel<<<grid, 256, SMEM_AV>>>(weights, v, ctx);
    }
}

// round 9
// speedup vs baseline: 1.3470x; 1.0102x over previous
#include <cuda_runtime.h>
#include <cstdint>
#include <cstddef>

#define Lq 2048
#define Hh 16
#define Cc 64
#define Bb 2

// Output layout: [context (B,L,H*C)] [scores (B,H,L,L)] [weights (B,H,L,L)]
#define OFF_S  ((size_t)Bb * Lq * Hh * Cc)
#define NSCORE ((size_t)Bb * Hh * Lq * Lq)
#define OFF_W  (OFF_S + NSCORE)

#define PADA 68
#define SMEM_SCORES (2 * 128 * PADA * 4)          // Qs + Ks = 69632 B

// av: 4-stage cp.async pipeline, 32-wide j chunks
#define AVJ 32
#define WROW 36
#define VROW 72
#define AV_STAGE (64 * WROW + AVJ * VROW)         // 4608 floats
#define AV_STAGES 4
#define SMEM_AV (AV_STAGES * AV_STAGE * 4)        // 73728 B

__device__ int g_mask_kind;  // 0 = u8/bool, 1 = int32, 2 = float32

// ---------------------------------------------------------------------------
__global__ void detect_mask_kernel(const void* __restrict__ m) {
    const unsigned int* w = (const unsigned int*)m;
    const int lane = threadIdx.x;
    bool i32 = true, f32 = true;
    for (int t = lane; t < 256; t += 32) {
        const unsigned int v = w[t];
        i32 = i32 && (v <= 1u);
        f32 = f32 && (v == 0u || v == 0x3F800000u);
    }
    const unsigned bi = __ballot_sync(0xffffffffu, i32);
    const unsigned bf = __ballot_sync(0xffffffffu, f32);
    if (lane == 0)
        g_mask_kind = (bi == 0xffffffffu) ? 1 : ((bf == 0xffffffffu) ? 2 : 0);
}

// ---------------------------------------------------------------------------
__device__ __forceinline__ float f2tf(float x) {
    unsigned r;
    asm("cvt.rna.tf32.f32 %0, %1;" : "=r"(r) : "f"(x));
    return __uint_as_float(r);
}

__device__ __forceinline__ void mma_tf32(float (&d)[4], const float (&a)[4],
                                         float b0, float b1) {
    asm volatile(
        "mma.sync.aligned.m16n8k8.row.col.f32.tf32.tf32.f32 "
        "{%0,%1,%2,%3}, {%4,%5,%6,%7}, {%8,%9}, {%0,%1,%2,%3};"
        : "+f"(d[0]), "+f"(d[1]), "+f"(d[2]), "+f"(d[3])
        : "r"(__float_as_uint(a[0])), "r"(__float_as_uint(a[1])),
          "r"(__float_as_uint(a[2])), "r"(__float_as_uint(a[3])),
          "r"(__float_as_uint(b0)), "r"(__float_as_uint(b1)));
}

__device__ __forceinline__ void cp16(void* s, const void* g) {
    const unsigned saddr = (unsigned)__cvta_generic_to_shared(s);
    asm volatile("cp.async.cg.shared.global [%0], [%1], 16;"
                 :: "r"(saddr), "l"(g));
}

// ---------------------------------------------------------------------------
// Kernel 1: scores = QK^T + edge. 128x128 tile, K=64 one pass.
// grid.x = jb*2 + b so both batches of the same (h, jb) are launch-adjacent
// and the edge tile is read from DRAM once (second reader hits L2).
// ---------------------------------------------------------------------------
__global__ __launch_bounds__(256) void scores_kernel(
    const float* __restrict__ q, const float* __restrict__ k,
    const float* __restrict__ edge, float* __restrict__ out_scores) {
    extern __shared__ float sm[];
    float* Qs = sm;                 // [128][PADA] : [i][c]
    float* Ks = sm + 128 * PADA;    // [128][PADA] : [j][c]

    const int h = blockIdx.z;                 // 0..15
    const int b = blockIdx.x & 1;             // batch folded into x
    const int jb = blockIdx.x >> 1;           // 0..15
    const int bh = b * Hh + h;
    const int i0 = blockIdx.y << 7;
    const int j0 = jb << 7;
    const int tid = threadIdx.x;

#pragma unroll
    for (int r = 0; r < 8; r++) {
        const int idx = r * 256 + tid;
        const int row = idx >> 4;
        const int c4 = (idx & 15) * 4;
        const float4 vq = *(const float4*)(q +
            ((size_t)(b * Lq + i0 + row) * Hh + h) * Cc + c4);
        float* dq = &Qs[row * PADA + c4];
        dq[0] = f2tf(vq.x); dq[1] = f2tf(vq.y);
        dq[2] = f2tf(vq.z); dq[3] = f2tf(vq.w);
        const float4 vk = *(const float4*)(k +
            ((size_t)(b * Lq + j0 + row) * Hh + h) * Cc + c4);
        float* dk = &Ks[row * PADA + c4];
        dk[0] = f2tf(vk.x); dk[1] = f2tf(vk.y);
        dk[2] = f2tf(vk.z); dk[3] = f2tf(vk.w);
    }
    __syncthreads();

    const int warp = tid >> 5, lane = tid & 31;
    const int wi = warp >> 1, wj = warp & 1;
    const int ibase = wi * 32, jbase = wj * 64;
    const int gid = lane >> 2, qid = lane & 3;

    float acc[2][8][4] = {};

#pragma unroll
    for (int kk = 0; kk < 8; kk++) {
        const int k0 = kk * 8;
        float a[2][4];
#pragma unroll
        for (int m = 0; m < 2; m++) {
            const int rr = ibase + m * 16 + gid;
            a[m][0] = Qs[rr * PADA + k0 + qid];
            a[m][1] = Qs[(rr + 8) * PADA + k0 + qid];
            a[m][2] = Qs[rr * PADA + k0 + qid + 4];
            a[m][3] = Qs[(rr + 8) * PADA + k0 + qid + 4];
        }
#pragma unroll
        for (int n = 0; n < 8; n++) {
            const int cc = jbase + n * 8 + gid;
            const float b0 = Ks[cc * PADA + k0 + qid];
            const float b1 = Ks[cc * PADA + k0 + qid + 4];
            mma_tf32(acc[0][n], a[0], b0, b1);
            mma_tf32(acc[1][n], a[1], b0, b1);
        }
    }

#pragma unroll
    for (int m = 0; m < 2; m++) {
#pragma unroll
        for (int n = 0; n < 8; n++) {
            const int i = i0 + ibase + m * 16 + gid;
            const int j = j0 + jbase + n * 8 + 2 * qid;
            const size_t e0 = ((size_t)h * Lq + i) * Lq + j;
            const size_t s0 = ((size_t)bh * Lq + i) * Lq + j;
            const float2 ea = *(const float2*)(edge + e0);
            const float2 eb = *(const float2*)(edge + e0 + 8 * (size_t)Lq);
            float2 oa, ob;
            oa.x = acc[m][n][0] + ea.x; oa.y = acc[m][n][1] + ea.y;
            ob.x = acc[m][n][2] + eb.x; ob.y = acc[m][n][3] + eb.y;
            __stcs((float2*)(out_scores + s0), oa);
            __stcs((float2*)(out_scores + s0 + 8 * (size_t)Lq), ob);
        }
    }
}

// ---------------------------------------------------------------------------
// Kernel 2: masked softmax. Block index = i*32 + bh so the 32 blocks sharing
// mask[b,i,:] are launch-adjacent -> mask row stays in L2 (one DRAM fetch).
// ---------------------------------------------------------------------------
__global__ __launch_bounds__(256) void softmax_kernel(
    const float* __restrict__ scores, const void* __restrict__ mask,
    float* __restrict__ wout) {
    const int bh = blockIdx.x & 31;
    const int i  = blockIdx.x >> 5;
    const int b  = bh >> 4;
    const size_t soff = ((size_t)bh * Lq + i) * Lq;
    const size_t moff = ((size_t)(b * Lq + i)) * Lq;
    const int tid = threadIdx.x;
    const int kind = g_mask_kind;

    const float4* sp = (const float4*)(scores + soff);
    const float4 s0 = __ldcs(sp + tid);
    const float4 s1 = __ldcs(sp + 256 + tid);

    float mb[8];
    if (kind == 1) {
        const int4* mp = (const int4*)((const int*)mask + moff);
        const int4 m0 = mp[tid], m1 = mp[256 + tid];
        mb[0] = m0.x ? 1.f : 0.f; mb[1] = m0.y ? 1.f : 0.f;
        mb[2] = m0.z ? 1.f : 0.f; mb[3] = m0.w ? 1.f : 0.f;
        mb[4] = m1.x ? 1.f : 0.f; mb[5] = m1.y ? 1.f : 0.f;
        mb[6] = m1.z ? 1.f : 0.f; mb[7] = m1.w ? 1.f : 0.f;
    } else if (kind == 2) {
        const float4* mp = (const float4*)((const float*)mask + moff);
        const float4 m0 = mp[tid], m1 = mp[256 + tid];
        mb[0] = (m0.x != 0.f); mb[1] = (m0.y != 0.f);
        mb[2] = (m0.z != 0.f); mb[3] = (m0.w != 0.f);
        mb[4] = (m1.x != 0.f); mb[5] = (m1.y != 0.f);
        mb[6] = (m1.z != 0.f); mb[7] = (m1.w != 0.f);
    } else {
        const uchar4* mp = (const uchar4*)((const unsigned char*)mask + moff);
        const uchar4 m0 = mp[tid], m1 = mp[256 + tid];
        mb[0] = m0.x ? 1.f : 0.f; mb[1] = m0.y ? 1.f : 0.f;
        mb[2] = m0.z ? 1.f : 0.f; mb[3] = m0.w ? 1.f : 0.f;
        mb[4] = m1.x ? 1.f : 0.f; mb[5] = m1.y ? 1.f : 0.f;
        mb[6] = m1.z ? 1.f : 0.f; mb[7] = m1.w ? 1.f : 0.f;
    }

    const float sv[8] = {s0.x, s0.y, s0.z, s0.w, s1.x, s1.y, s1.z, s1.w};
    float x[8];
#pragma unroll
    for (int t = 0; t < 8; t++)
        x[t] = (mb[t] != 0.f) ? sv[t] * 0.125f : -1e18f;

    float mx = x[0];
#pragma unroll
    for (int t = 1; t < 8; t++) mx = fmaxf(mx, x[t]);
#pragma unroll
    for (int o = 16; o; o >>= 1) mx = fmaxf(mx, __shfl_xor_sync(0xffffffffu, mx, o));

    __shared__ float red_max[8];
    __shared__ float red_sum[8];
    if ((tid & 31) == 0) red_max[tid >> 5] = mx;
    __syncthreads();
    mx = red_max[0];
#pragma unroll
    for (int wi = 1; wi < 8; wi++) mx = fmaxf(mx, red_max[wi]);

    float e[8];
    float s = 0.0f;
#pragma unroll
    for (int t = 0; t < 8; t++) {
        e[t] = __expf(x[t] - mx);
        s += e[t];
    }
#pragma unroll
    for (int o = 16; o; o >>= 1) s += __shfl_xor_sync(0xffffffffu, s, o);
    if ((tid & 31) == 0) red_sum[tid >> 5] = s;
    __syncthreads();
    s = red_sum[0];
#pragma unroll
    for (int wi = 1; wi < 8; wi++) s += red_sum[wi];

    const float inv = 1.0f / s;
    float4 w0, w1;
    w0.x = e[0] * inv * mb[0]; w0.y = e[1] * inv * mb[1];
    w0.z = e[2] * inv * mb[2]; w0.w = e[3] * inv * mb[3];
    w1.x = e[4] * inv * mb[4]; w1.y = e[5] * inv * mb[5];
    w1.z = e[6] * inv * mb[6]; w1.w = e[7] * inv * mb[7];
    float4* wp = (float4*)(wout + soff);
    __stcs(wp + tid, w0);
    __stcs(wp + 256 + tid, w1);
}

// ---------------------------------------------------------------------------
// Kernel 3: ctx = W * V. CTA 64(i) x 64(c), j chunks of 32.
// 4-stage cp.async pipeline, one syncthreads/iter, rna tf32 on fragments.
// ---------------------------------------------------------------------------
__global__ __launch_bounds__(256, 3) void av_kernel(
    const float* __restrict__ w, const float* __restrict__ v,
    float* __restrict__ ctx) {
    extern __shared__ float sm[];

    const int bh = blockIdx.y;
    const int b = bh >> 4, h = bh & 15;
    const int i0 = blockIdx.x << 6;
    const int tid = threadIdx.x;
    const int warp = tid >> 5, lane = tid & 31;
    const int wi = warp >> 1, wc = warp & 1;
    const int ibase = wi * 16, cbase = wc * 32;
    const int gid = lane >> 2, qid = lane & 3;

    const int wrow = tid >> 3;
    const int wc4  = (tid & 7) * 4;
    const int vrow = tid >> 4;
    const int vc4  = (tid & 15) * 4;

    auto issue = [&](int jt, int s) {
        float* Wb = sm + s * AV_STAGE;
        float* Vb = Wb + 64 * WROW;
        const int j0 = jt * AVJ;
#pragma unroll
        for (int t = 0; t < 2; t++) {
            const int row = t * 32 + wrow;
            cp16(&Wb[row * WROW + wc4],
                 w + ((size_t)bh * Lq + i0 + row) * Lq + j0 + wc4);
        }
#pragma unroll
        for (int t = 0; t < 2; t++) {
            const int row = t * 16 + vrow;
            cp16(&Vb[row * VROW + vc4],
                 v + ((size_t)(b * Lq + j0 + row) * Hh + h) * Cc + vc4);
        }
        asm volatile("cp.async.commit_group;");
    };

    float acc[4][4] = {};

    const int NT = Lq / AVJ;   // 64
    issue(0, 0);
    issue(1, 1);
    issue(2, 2);

    for (int jt = 0; jt < NT; jt++) {
        asm volatile("cp.async.wait_group 2;");
        __syncthreads();
        if (jt + 3 < NT) {
            issue(jt + 3, (jt + 3) & 3);
        } else {
            asm volatile("cp.async.commit_group;");
        }

        const float* Wb = sm + (jt & 3) * AV_STAGE;
        const float* Vb = Wb + 64 * WROW;

#pragma unroll
        for (int kk = 0; kk < 4; kk++) {
            const int k0 = kk * 8;
            float a[4];
            const int rr = ibase + gid;
            a[0] = f2tf(Wb[rr * WROW + k0 + qid]);
            a[1] = f2tf(Wb[(rr + 8) * WROW + k0 + qid]);
            a[2] = f2tf(Wb[rr * WROW + k0 + qid + 4]);
            a[3] = f2tf(Wb[(rr + 8) * WROW + k0 + qid + 4]);
#pragma unroll
            for (int n = 0; n < 4; n++) {
                const int cc = cbase + n * 8 + gid;
                const float b0 = f2tf(Vb[(k0 + qid) * VROW + cc]);
                const float b1 = f2tf(Vb[(k0 + qid + 4) * VROW + cc]);
                mma_tf32(acc[n], a, b0, b1);
            }
        }
    }

#pragma unroll
    for (int n = 0; n < 4; n++) {
        const int i = i0 + ibase + gid;
        const int c = h * Cc + cbase + n * 8 + 2 * qid;
        float2 oa, ob;
        oa.x = acc[n][0]; oa.y = acc[n][1];
        ob.x = acc[n][2]; ob.y = acc[n][3];
        *(float2*)(ctx + ((size_t)(b * Lq + i)) * (Hh * Cc) + c) = oa;
        *(float2*)(ctx + ((size_t)(b * Lq + i + 8)) * (Hh * Cc) + c) = ob;
    }
}

// ---------------------------------------------------------------------------
extern "C" void kernel_launch(void* const* d_in, const int* in_sizes, int n_in,
                              void* d_out, int out_size) {
    (void)in_sizes; (void)n_in; (void)out_size;
    const float* q    = (const float*)d_in[0];
    const float* k    = (const float*)d_in[1];
    const float* v    = (const float*)d_in[2];
    const void*  mask = d_in[3];
    const float* edge = (const float*)d_in[4];

    float* out     = (float*)d_out;
    float* ctx     = out;
    float* scores  = out + OFF_S;
    float* weights = out + OFF_W;

    cudaFuncSetAttribute(scores_kernel,
        cudaFuncAttributeMaxDynamicSharedMemorySize, SMEM_SCORES);
    cudaFuncSetAttribute(av_kernel,
        cudaFuncAttributeMaxDynamicSharedMemorySize, SMEM_AV);

    detect_mask_kernel<<<1, 32>>>(mask);

    {
        dim3 grid(2 * (Lq / 128), Lq / 128, Hh);
        scores_kernel<<<grid, 256, SMEM_SCORES>>>(q, k, edge, scores);
    }
    {
        softmax_kernel<<<Bb * Hh * Lq, 256>>>(scores, mask, weights);
    }
    {
        dim3 grid(Lq / 64, Bb * Hh);
        av_kernel<<<grid, 256, SMEM_AV>>>(weights, v, ctx);
    }
}